// round 3
// baseline (speedup 1.0000x reference)
#include <cuda_runtime.h>
#include <math.h>

#define Bz   16
#define Cc   256
#define Nn   2048
#define DQ   64
#define RR   189          // 3 * (2*BINS-1)
#define NNsz ((size_t)Nn * Nn)

// ---------------- scratch (device globals; no runtime allocations) -------------
__device__ float g_W[384 * Cc];              // [Wq;Wk;Wv]
__device__ float g_LT[RR * DQ];              // [x_lt;y_lt;z_lt]
__device__ int   g_dpack[Bz * Nn];           // packed discrete (5 bits/axis)
__device__ float g_q[Bz * DQ * Nn];
__device__ float g_k[Bz * DQ * Nn];
__device__ float g_v[(size_t)Bz * Cc * Nn];
__device__ float g_qlt[(size_t)Bz * Nn * RR];
__device__ float g_T[(size_t)Bz * Nn * 96];  // per-row shifted bias tables
__device__ float g_E[(size_t)Bz * Nn * Nn];  // exp(energy) (268 MB)
__device__ float g_rowpart[16 * Bz * Nn];
__device__ float g_rowinv[Bz * Nn];
__device__ float g_colpart[8 * Bz * Nn];
__device__ float g_colinv[Bz * Nn];
__device__ float g_xmr[(size_t)Bz * Cc * Nn];

// ------------------------------- prep -----------------------------------------
__global__ void prep_kernel(const float* __restrict__ Wq, const float* __restrict__ Wk,
                            const float* __restrict__ Wv,
                            const float* __restrict__ xlt, const float* __restrict__ ylt,
                            const float* __restrict__ zlt,
                            const int* __restrict__ disc) {
    int t = blockIdx.x * blockDim.x + threadIdx.x;
    if (t < 64 * Cc)          g_W[t] = Wq[t];
    else if (t < 128 * Cc)    g_W[t] = Wk[t - 64 * Cc];
    else if (t < 384 * Cc)    g_W[t] = Wv[t - 128 * Cc];
    if (t < RR * DQ) {
        int ax = t / (63 * DQ);
        const float* src = (ax == 0) ? xlt : ((ax == 1) ? ylt : zlt);
        g_LT[t] = src[t - ax * 63 * DQ];
    }
    if (t < Bz * Nn) {
        const int* d = disc + t * 3;
        g_dpack[t] = d[0] | (d[1] << 5) | (d[2] << 10);
    }
}

// ------------------- QKV projection: [384x256] @ x[b] -> q,k,v -----------------
__global__ __launch_bounds__(256, 2) void qkv_kernel(const float* __restrict__ x,
                                                     const float* __restrict__ bv) {
    const int b = blockIdx.z, oct = blockIdx.y, nt = blockIdx.x;
    const int oc0 = oct * 128, n0 = nt * 128;
    const int t = threadIdx.x, tr = t >> 4, tc = t & 15;
    __shared__ float Ws[32][132];
    __shared__ float Xs[32][132];
    const float* xb = x + (size_t)b * Cc * Nn + n0;
    float acc[8][8] = {};
    float4 wr[4], xr4[4];
    #pragma unroll
    for (int u = 0; u < 4; u++) {
        int idx = (u * 256 + t) * 4;
        wr[u]  = *(const float4*)&g_W[(oc0 + (idx >> 5)) * Cc + (idx & 31)];
        xr4[u] = *(const float4*)&xb[(size_t)(idx >> 7) * Nn + (idx & 127)];
    }
    int k0 = 0;
    while (true) {
        #pragma unroll
        for (int u = 0; u < 4; u++) {
            int idx = (u * 256 + t) * 4;
            int oc = idx >> 5, kk = idx & 31;
            Ws[kk + 0][oc] = wr[u].x; Ws[kk + 1][oc] = wr[u].y;
            Ws[kk + 2][oc] = wr[u].z; Ws[kk + 3][oc] = wr[u].w;
            *(float4*)&Xs[idx >> 7][idx & 127] = xr4[u];
        }
        __syncthreads();
        k0 += 32;
        bool more = (k0 < Cc);
        if (more) {
            #pragma unroll
            for (int u = 0; u < 4; u++) {
                int idx = (u * 256 + t) * 4;
                wr[u]  = *(const float4*)&g_W[(oc0 + (idx >> 5)) * Cc + k0 + (idx & 31)];
                xr4[u] = *(const float4*)&xb[(size_t)(k0 + (idx >> 7)) * Nn + (idx & 127)];
            }
        }
        #pragma unroll 8
        for (int kk = 0; kk < 32; kk++) {
            float4 a0 = *(float4*)&Ws[kk][tr * 8], a1 = *(float4*)&Ws[kk][tr * 8 + 4];
            float4 b0 = *(float4*)&Xs[kk][tc * 8], b1 = *(float4*)&Xs[kk][tc * 8 + 4];
            float a[8]  = {a0.x, a0.y, a0.z, a0.w, a1.x, a1.y, a1.z, a1.w};
            float bb[8] = {b0.x, b0.y, b0.z, b0.w, b1.x, b1.y, b1.z, b1.w};
            #pragma unroll
            for (int i = 0; i < 8; i++)
                #pragma unroll
                for (int j = 0; j < 8; j++)
                    acc[i][j] += a[i] * bb[j];
        }
        __syncthreads();
        if (!more) break;
    }
    #pragma unroll
    for (int i = 0; i < 8; i++) {
        int oc = oc0 + tr * 8 + i;
        float* dst; float bias = 0.f;
        if (oc < 64)        dst = g_q + ((size_t)b * DQ + oc) * Nn;
        else if (oc < 128)  dst = g_k + ((size_t)b * DQ + (oc - 64)) * Nn;
        else { dst = g_v + ((size_t)b * Cc + (oc - 128)) * Nn; bias = bv[oc - 128]; }
        #pragma unroll
        for (int j = 0; j < 8; j++) dst[n0 + tc * 8 + j] = acc[i][j] + bias;
    }
}

// ---------------------- qlt = q @ LT^T : [B,N,189] -----------------------------
__global__ __launch_bounds__(256) void qlt_kernel() {
    const int b = blockIdx.z, nt = blockIdx.y, rt = blockIdx.x;
    const int n0 = nt * 128, r0 = rt * 64;
    const int t = threadIdx.x, tr = t >> 4, tc = t & 15;
    __shared__ float Qs[64][128];
    __shared__ float Ls[64][64];
    const float* qb = g_q + (size_t)b * DQ * Nn + n0;
    #pragma unroll
    for (int u = 0; u < 8; u++) {
        int idx = (u * 256 + t) * 4;
        *(float4*)&Qs[idx >> 7][idx & 127] =
            *(const float4*)&qb[(size_t)(idx >> 7) * Nn + (idx & 127)];
    }
    #pragma unroll
    for (int u = 0; u < 4; u++) {
        int idx = (u * 256 + t) * 4;
        int rr = idx >> 6, kk = idx & 63;
        float4 w4 = make_float4(0.f, 0.f, 0.f, 0.f);
        if (r0 + rr < RR) w4 = *(const float4*)&g_LT[(r0 + rr) * DQ + kk];
        Ls[kk + 0][rr] = w4.x; Ls[kk + 1][rr] = w4.y;
        Ls[kk + 2][rr] = w4.z; Ls[kk + 3][rr] = w4.w;
    }
    __syncthreads();
    float acc[8][4] = {};
    #pragma unroll 8
    for (int kk = 0; kk < 64; kk++) {
        float4 a0 = *(float4*)&Qs[kk][tr * 8], a1 = *(float4*)&Qs[kk][tr * 8 + 4];
        float4 b0 = *(float4*)&Ls[kk][tc * 4];
        float a[8]  = {a0.x, a0.y, a0.z, a0.w, a1.x, a1.y, a1.z, a1.w};
        float bb[4] = {b0.x, b0.y, b0.z, b0.w};
        #pragma unroll
        for (int i = 0; i < 8; i++)
            #pragma unroll
            for (int j = 0; j < 4; j++)
                acc[i][j] += a[i] * bb[j];
    }
    #pragma unroll
    for (int i = 0; i < 8; i++) {
        int n = n0 + tr * 8 + i;
        float* dst = g_qlt + ((size_t)b * Nn + n) * RR;
        #pragma unroll
        for (int j = 0; j < 4; j++) {
            int rg = r0 + tc * 4 + j;
            if (rg < RR) dst[rg] = acc[i][j];
        }
    }
}

// ------------- gather per-row shifted bias tables T[b,n,ax*32+j] ---------------
__global__ void tgather_kernel() {
    int o = blockIdx.x * 256 + threadIdx.x;
    if (o >= Bz * Nn * 96) return;
    int ng = o / 96;
    int rem = o - ng * 96;
    int ax = rem >> 5, j = rem & 31;
    int dn = (g_dpack[ng] >> (5 * ax)) & 31;
    g_T[o] = g_qlt[(size_t)ng * RR + ax * 63 + j + 31 - dn];
}

// -------- pass A: E = exp(q.k + bias), row partial sums (deterministic) --------
__global__ __launch_bounds__(256, 1) void energy_kernel() {
    extern __shared__ float sm[];
    float* Qs = sm;                 // [64][128]
    float* Ks = sm + 8192;          // [64][128]
    float* Ts = sm + 16384;         // [128][96]
    int*   Ds = (int*)(sm + 28672); // [128]
    const int b = blockIdx.z, nt = blockIdx.y, mt = blockIdx.x;
    const int n0 = nt * 128, m0 = mt * 128;
    const int t = threadIdx.x, tr = t >> 4, tc = t & 15;
    const float* qb = g_q + (size_t)b * DQ * Nn + n0;
    const float* kb = g_k + (size_t)b * DQ * Nn + m0;
    const float* tb = g_T + ((size_t)b * Nn + n0) * 96;
    #pragma unroll
    for (int u = 0; u < 8; u++) {
        int idx = (u * 256 + t) * 4;
        int kk = idx >> 7, c = idx & 127;
        *(float4*)&Qs[idx] = *(const float4*)&qb[(size_t)kk * Nn + c];
        *(float4*)&Ks[idx] = *(const float4*)&kb[(size_t)kk * Nn + c];
    }
    #pragma unroll
    for (int u = 0; u < 12; u++) {
        int idx = (u * 256 + t) * 4;
        *(float4*)&Ts[idx] = *(const float4*)&tb[idx];
    }
    if (t < 128) Ds[t] = g_dpack[b * Nn + m0 + t];
    __syncthreads();

    float acc[8][8] = {};
    #pragma unroll 8
    for (int kk = 0; kk < 64; kk++) {
        float4 a0 = *(float4*)&Qs[kk * 128 + tr * 8];
        float4 a1 = *(float4*)&Qs[kk * 128 + tr * 8 + 4];
        float4 b0 = *(float4*)&Ks[kk * 128 + tc * 8];
        float4 b1 = *(float4*)&Ks[kk * 128 + tc * 8 + 4];
        float a[8]  = {a0.x, a0.y, a0.z, a0.w, a1.x, a1.y, a1.z, a1.w};
        float bb[8] = {b0.x, b0.y, b0.z, b0.w, b1.x, b1.y, b1.z, b1.w};
        #pragma unroll
        for (int i = 0; i < 8; i++)
            #pragma unroll
            for (int j = 0; j < 8; j++)
                acc[i][j] += a[i] * bb[j];
    }

    int dp[8];
    #pragma unroll
    for (int j = 0; j < 8; j++) dp[j] = Ds[tc * 8 + j];
    float* Eb = g_E + (size_t)b * NNsz;
    float rsum[8];
    #pragma unroll
    for (int i = 0; i < 8; i++) {
        const float* Tr = Ts + (tr * 8 + i) * 96;
        float o[8]; float rs = 0.f;
        #pragma unroll
        for (int j = 0; j < 8; j++) {
            int d = dp[j];
            float e = acc[i][j] + Tr[d & 31] + Tr[32 + ((d >> 5) & 31)]
                                + Tr[64 + ((d >> 10) & 31)];
            float v = __expf(e);   // |e| << 88: no max-subtraction needed
            o[j] = v; rs += v;
        }
        rsum[i] = rs;
        float* Er = Eb + (size_t)(n0 + tr * 8 + i) * Nn + m0 + tc * 8;
        *(float4*)&Er[0] = make_float4(o[0], o[1], o[2], o[3]);
        *(float4*)&Er[4] = make_float4(o[4], o[5], o[6], o[7]);
    }
    #pragma unroll
    for (int i = 0; i < 8; i++) {
        #pragma unroll
        for (int mk = 1; mk < 16; mk <<= 1)
            rsum[i] += __shfl_xor_sync(0xffffffffu, rsum[i], mk);
    }
    if (tc == 0) {
        float* rp = g_rowpart + mt * (Bz * Nn) + b * Nn + n0 + tr * 8;
        #pragma unroll
        for (int i = 0; i < 8; i++) rp[i] = rsum[i];
    }
}

__global__ void reduce_row_kernel() {
    int i = blockIdx.x * 256 + threadIdx.x;
    if (i >= Bz * Nn) return;
    float s = 0.f;
    #pragma unroll
    for (int p = 0; p < 16; p++) s += g_rowpart[p * (Bz * Nn) + i];
    g_rowinv[i] = 1.0f / s;
}

// ------------- pass B: column partial sums of attn (= E * rowinv) --------------
__global__ void colsum_kernel() {
    const int b = blockIdx.z;
    const int m = blockIdx.x * 256 + threadIdx.x;
    const int n0 = blockIdx.y * 256;
    __shared__ float ri[256];
    ri[threadIdx.x] = g_rowinv[b * Nn + n0 + threadIdx.x];
    __syncthreads();
    const float* Ep = g_E + (size_t)b * NNsz + (size_t)n0 * Nn + m;
    float acc = 0.f;
    #pragma unroll 8
    for (int nn = 0; nn < 256; nn++)
        acc += Ep[(size_t)nn * Nn] * ri[nn];
    g_colpart[blockIdx.y * (Bz * Nn) + b * Nn + m] = acc;
}

__global__ void reduce_col_kernel() {
    int i = blockIdx.x * 256 + threadIdx.x;
    if (i >= Bz * Nn) return;
    float s = 0.f;
    #pragma unroll
    for (int p = 0; p < 8; p++) s += g_colpart[p * (Bz * Nn) + i];
    g_colinv[i] = 1.0f / (1e-9f + s);
}

// ------ pass C: x_r = v @ (E*rowinv*colinv); store xmr = x - x_r ----------------
__global__ __launch_bounds__(256, 2) void xr_kernel(const float* __restrict__ x) {
    const int b = blockIdx.z, dt = blockIdx.y, mt = blockIdx.x;
    const int d0 = dt * 128, m0 = mt * 128;
    const int t = threadIdx.x, tr = t >> 4, tc = t & 15;
    __shared__ float Vs[16][132];
    __shared__ float Es[16][132];
    const float* vb = g_v + ((size_t)b * Cc + d0) * Nn;
    const float* Eb = g_E + (size_t)b * NNsz + m0;
    const float* ri = g_rowinv + b * Nn;
    float acc[8][8] = {};
    float4 vr[2], er[2];
    #pragma unroll
    for (int u = 0; u < 2; u++) {
        int idx = (u * 256 + t) * 4;
        vr[u] = *(const float4*)&vb[(size_t)(idx >> 4) * Nn + (idx & 15)];
        float s = ri[idx >> 7];
        float4 e4 = *(const float4*)&Eb[(size_t)(idx >> 7) * Nn + (idx & 127)];
        e4.x *= s; e4.y *= s; e4.z *= s; e4.w *= s;
        er[u] = e4;
    }
    int k0 = 0;
    while (true) {
        #pragma unroll
        for (int u = 0; u < 2; u++) {
            int idx = (u * 256 + t) * 4;
            int dd = idx >> 4, kk = idx & 15;
            Vs[kk + 0][dd] = vr[u].x; Vs[kk + 1][dd] = vr[u].y;
            Vs[kk + 2][dd] = vr[u].z; Vs[kk + 3][dd] = vr[u].w;
            *(float4*)&Es[idx >> 7][idx & 127] = er[u];
        }
        __syncthreads();
        k0 += 16;
        bool more = (k0 < Nn);
        if (more) {
            #pragma unroll
            for (int u = 0; u < 2; u++) {
                int idx = (u * 256 + t) * 4;
                vr[u] = *(const float4*)&vb[(size_t)(idx >> 4) * Nn + k0 + (idx & 15)];
                float s = ri[k0 + (idx >> 7)];
                float4 e4 = *(const float4*)&Eb[(size_t)(k0 + (idx >> 7)) * Nn + (idx & 127)];
                e4.x *= s; e4.y *= s; e4.z *= s; e4.w *= s;
                er[u] = e4;
            }
        }
        #pragma unroll 8
        for (int kk = 0; kk < 16; kk++) {
            float4 a0 = *(float4*)&Vs[kk][tr * 8], a1 = *(float4*)&Vs[kk][tr * 8 + 4];
            float4 b0 = *(float4*)&Es[kk][tc * 8], b1 = *(float4*)&Es[kk][tc * 8 + 4];
            float a[8]  = {a0.x, a0.y, a0.z, a0.w, a1.x, a1.y, a1.z, a1.w};
            float bb[8] = {b0.x, b0.y, b0.z, b0.w, b1.x, b1.y, b1.z, b1.w};
            #pragma unroll
            for (int i = 0; i < 8; i++)
                #pragma unroll
                for (int j = 0; j < 8; j++)
                    acc[i][j] += a[i] * bb[j];
        }
        __syncthreads();
        if (!more) break;
    }
    const float* ci = g_colinv + b * Nn + m0 + tc * 8;
    float cv[8];
    #pragma unroll
    for (int j = 0; j < 8; j++) cv[j] = ci[j];
    #pragma unroll
    for (int i = 0; i < 8; i++) {
        int d = d0 + tr * 8 + i;
        const float* xrow = x + ((size_t)b * Cc + d) * Nn + m0 + tc * 8;
        float* orow = g_xmr + ((size_t)b * Cc + d) * Nn + m0 + tc * 8;
        #pragma unroll
        for (int j = 0; j < 8; j++)
            orow[j] = xrow[j] - acc[i][j] * cv[j];
    }
}

// ------- pass D: out = x + relu(BN(Wt @ xmr + bt)) ------------------------------
__global__ __launch_bounds__(256, 2) void trans_kernel(
    const float* __restrict__ x, const float* __restrict__ Wt,
    const float* __restrict__ bt, const float* __restrict__ gamma,
    const float* __restrict__ beta, const float* __restrict__ rmean,
    const float* __restrict__ rvar, float* __restrict__ out) {
    const int b = blockIdx.z, ot = blockIdx.y, mt = blockIdx.x;
    const int o0 = ot * 128, m0 = mt * 128;
    const int t = threadIdx.x, tr = t >> 4, tc = t & 15;
    __shared__ float Ws[32][132];
    __shared__ float Xs[32][132];
    const float* xb = g_xmr + (size_t)b * Cc * Nn + m0;
    float acc[8][8] = {};
    float4 wr[4], xr4[4];
    #pragma unroll
    for (int u = 0; u < 4; u++) {
        int idx = (u * 256 + t) * 4;
        wr[u]  = *(const float4*)&Wt[(o0 + (idx >> 5)) * Cc + (idx & 31)];
        xr4[u] = *(const float4*)&xb[(size_t)(idx >> 7) * Nn + (idx & 127)];
    }
    int k0 = 0;
    while (true) {
        #pragma unroll
        for (int u = 0; u < 4; u++) {
            int idx = (u * 256 + t) * 4;
            int oc = idx >> 5, kk = idx & 31;
            Ws[kk + 0][oc] = wr[u].x; Ws[kk + 1][oc] = wr[u].y;
            Ws[kk + 2][oc] = wr[u].z; Ws[kk + 3][oc] = wr[u].w;
            *(float4*)&Xs[idx >> 7][idx & 127] = xr4[u];
        }
        __syncthreads();
        k0 += 32;
        bool more = (k0 < Cc);
        if (more) {
            #pragma unroll
            for (int u = 0; u < 4; u++) {
                int idx = (u * 256 + t) * 4;
                wr[u]  = *(const float4*)&Wt[(o0 + (idx >> 5)) * Cc + k0 + (idx & 31)];
                xr4[u] = *(const float4*)&xb[(size_t)(k0 + (idx >> 7)) * Nn + (idx & 127)];
            }
        }
        #pragma unroll 8
        for (int kk = 0; kk < 32; kk++) {
            float4 a0 = *(float4*)&Ws[kk][tr * 8], a1 = *(float4*)&Ws[kk][tr * 8 + 4];
            float4 b0 = *(float4*)&Xs[kk][tc * 8], b1 = *(float4*)&Xs[kk][tc * 8 + 4];
            float a[8]  = {a0.x, a0.y, a0.z, a0.w, a1.x, a1.y, a1.z, a1.w};
            float bb[8] = {b0.x, b0.y, b0.z, b0.w, b1.x, b1.y, b1.z, b1.w};
            #pragma unroll
            for (int i = 0; i < 8; i++)
                #pragma unroll
                for (int j = 0; j < 8; j++)
                    acc[i][j] += a[i] * bb[j];
        }
        __syncthreads();
        if (!more) break;
    }
    #pragma unroll
    for (int i = 0; i < 8; i++) {
        int oc = o0 + tr * 8 + i;
        float inv = gamma[oc] * rsqrtf(rvar[oc] + 1e-5f);
        float mb  = bt[oc] - rmean[oc];
        float be  = beta[oc];
        const float* xrow = x + ((size_t)b * Cc + oc) * Nn + m0 + tc * 8;
        float* orow = out + ((size_t)b * Cc + oc) * Nn + m0 + tc * 8;
        #pragma unroll
        for (int j = 0; j < 8; j++) {
            float y = (acc[i][j] + mb) * inv + be;
            orow[j] = xrow[j] + fmaxf(y, 0.f);
        }
    }
}

// ------------------------------- launch ----------------------------------------
extern "C" void kernel_launch(void* const* d_in, const int* in_sizes, int n_in,
                              void* d_out, int out_size) {
    const float* x        = (const float*)d_in[0];
    const int*   discrete = (const int*)  d_in[1];
    // d_in[2] = xyz (unused by the reference math)
    const float* Wq    = (const float*)d_in[3];
    const float* Wk    = (const float*)d_in[4];
    const float* Wv    = (const float*)d_in[5];
    const float* bv    = (const float*)d_in[6];
    const float* x_lt  = (const float*)d_in[7];
    const float* y_lt  = (const float*)d_in[8];
    const float* z_lt  = (const float*)d_in[9];
    const float* Wt    = (const float*)d_in[10];
    const float* bt    = (const float*)d_in[11];
    const float* gamma = (const float*)d_in[12];
    const float* beta  = (const float*)d_in[13];
    const float* rmean = (const float*)d_in[14];
    const float* rvar  = (const float*)d_in[15];
    float* out = (float*)d_out;

    static const size_t kEnergySmem = 28672 * sizeof(float) + 128 * sizeof(int);
    cudaFuncSetAttribute(energy_kernel,
                         cudaFuncAttributeMaxDynamicSharedMemorySize,
                         (int)kEnergySmem);

    prep_kernel<<<(384 * Cc + 255) / 256, 256>>>(Wq, Wk, Wv, x_lt, y_lt, z_lt, discrete);

    dim3 g1(Nn / 128, 3, Bz);
    qkv_kernel<<<g1, 256>>>(x, bv);

    dim3 g2(3, Nn / 128, Bz);
    qlt_kernel<<<g2, 256>>>();

    tgather_kernel<<<(Bz * Nn * 96 + 255) / 256, 256>>>();

    dim3 g3(Nn / 128, Nn / 128, Bz);
    energy_kernel<<<g3, 256, kEnergySmem>>>();

    reduce_row_kernel<<<(Bz * Nn + 255) / 256, 256>>>();

    dim3 g4(Nn / 256, Nn / 256, Bz);
    colsum_kernel<<<g4, 256>>>();

    reduce_col_kernel<<<(Bz * Nn + 255) / 256, 256>>>();

    dim3 g5(Nn / 128, Cc / 128, Bz);
    xr_kernel<<<g5, 256>>>(x);

    dim3 g6(Nn / 128, Cc / 128, Bz);
    trans_kernel<<<g6, 256>>>(x, Wt, bt, gamma, beta, rmean, rvar, out);
}

// round 17
// speedup vs baseline: 1.4917x; 1.4917x over previous
#include <cuda_runtime.h>
#include <math.h>

#define Bz   16
#define Cc   256
#define Nn   2048
#define DQ   64
#define RR   189          // 3 * (2*BINS-1)
#define NNsz ((size_t)Nn * Nn)

// ---------------- scratch (device globals; no runtime allocations) -------------
__device__ float g_W[384 * Cc];              // [Wq;Wk;Wv]
__device__ float g_LT[RR * DQ];              // [x_lt;y_lt;z_lt]
__device__ int   g_dpack[Bz * Nn];           // packed discrete (5 bits/axis)
__device__ float g_q[Bz * DQ * Nn];
__device__ float g_k[Bz * DQ * Nn];
__device__ float g_v[(size_t)Bz * Cc * Nn];
__device__ float g_qlt[(size_t)Bz * Nn * RR];
__device__ float g_T[(size_t)Bz * Nn * 96];  // per-row shifted bias tables
__device__ float g_E[(size_t)Bz * Nn * Nn];  // exp(energy) (268 MB)
__device__ float g_rowpart[16 * Bz * Nn];
__device__ float g_rowinv[Bz * Nn];
__device__ float g_xmr[(size_t)Bz * Cc * Nn];

// ------------------------------- helpers ---------------------------------------
__device__ __forceinline__ float cvt_tf32(float v) {
    float o;
    asm("cvt.rna.tf32.f32 %0, %1;" : "=f"(o) : "f"(v));
    return o;
}
__device__ __forceinline__ void mma_tf32(float* c, const unsigned* a, const unsigned* bb) {
    asm("mma.sync.aligned.m16n8k8.row.col.f32.tf32.tf32.f32 "
        "{%0,%1,%2,%3},{%4,%5,%6,%7},{%8,%9},{%0,%1,%2,%3};"
        : "+f"(c[0]), "+f"(c[1]), "+f"(c[2]), "+f"(c[3])
        : "r"(a[0]), "r"(a[1]), "r"(a[2]), "r"(a[3]), "r"(bb[0]), "r"(bb[1]));
}

// ------------------------------- prep -----------------------------------------
__global__ void prep_kernel(const float* __restrict__ Wq, const float* __restrict__ Wk,
                            const float* __restrict__ Wv,
                            const float* __restrict__ xlt, const float* __restrict__ ylt,
                            const float* __restrict__ zlt,
                            const int* __restrict__ disc) {
    int t = blockIdx.x * blockDim.x + threadIdx.x;
    if (t < 64 * Cc)          g_W[t] = Wq[t];
    else if (t < 128 * Cc)    g_W[t] = Wk[t - 64 * Cc];
    else if (t < 384 * Cc)    g_W[t] = Wv[t - 128 * Cc];
    if (t < RR * DQ) {
        int ax = t / (63 * DQ);
        const float* src = (ax == 0) ? xlt : ((ax == 1) ? ylt : zlt);
        g_LT[t] = src[t - ax * 63 * DQ];
    }
    if (t < Bz * Nn) {
        const int* d = disc + t * 3;
        g_dpack[t] = d[0] | (d[1] << 5) | (d[2] << 10);
    }
}

// ------------------- QKV projection: [384x256] @ x[b] -> q,k,v -----------------
__global__ __launch_bounds__(256, 2) void qkv_kernel(const float* __restrict__ x,
                                                     const float* __restrict__ bv) {
    const int b = blockIdx.z, oct = blockIdx.y, nt = blockIdx.x;
    const int oc0 = oct * 128, n0 = nt * 128;
    const int t = threadIdx.x, tr = t >> 4, tc = t & 15;
    __shared__ float Ws[32][132];
    __shared__ float Xs[32][132];
    const float* xb = x + (size_t)b * Cc * Nn + n0;
    float acc[8][8] = {};
    float4 wr[4], xr4[4];
    #pragma unroll
    for (int u = 0; u < 4; u++) {
        int idx = (u * 256 + t) * 4;
        wr[u]  = *(const float4*)&g_W[(oc0 + (idx >> 5)) * Cc + (idx & 31)];
        xr4[u] = *(const float4*)&xb[(size_t)(idx >> 7) * Nn + (idx & 127)];
    }
    int k0 = 0;
    while (true) {
        #pragma unroll
        for (int u = 0; u < 4; u++) {
            int idx = (u * 256 + t) * 4;
            int oc = idx >> 5, kk = idx & 31;
            Ws[kk + 0][oc] = wr[u].x; Ws[kk + 1][oc] = wr[u].y;
            Ws[kk + 2][oc] = wr[u].z; Ws[kk + 3][oc] = wr[u].w;
            *(float4*)&Xs[idx >> 7][idx & 127] = xr4[u];
        }
        __syncthreads();
        k0 += 32;
        bool more = (k0 < Cc);
        if (more) {
            #pragma unroll
            for (int u = 0; u < 4; u++) {
                int idx = (u * 256 + t) * 4;
                wr[u]  = *(const float4*)&g_W[(oc0 + (idx >> 5)) * Cc + k0 + (idx & 31)];
                xr4[u] = *(const float4*)&xb[(size_t)(k0 + (idx >> 7)) * Nn + (idx & 127)];
            }
        }
        #pragma unroll 8
        for (int kk = 0; kk < 32; kk++) {
            float4 a0 = *(float4*)&Ws[kk][tr * 8], a1 = *(float4*)&Ws[kk][tr * 8 + 4];
            float4 b0 = *(float4*)&Xs[kk][tc * 8], b1 = *(float4*)&Xs[kk][tc * 8 + 4];
            float a[8]  = {a0.x, a0.y, a0.z, a0.w, a1.x, a1.y, a1.z, a1.w};
            float bb[8] = {b0.x, b0.y, b0.z, b0.w, b1.x, b1.y, b1.z, b1.w};
            #pragma unroll
            for (int i = 0; i < 8; i++)
                #pragma unroll
                for (int j = 0; j < 8; j++)
                    acc[i][j] += a[i] * bb[j];
        }
        __syncthreads();
        if (!more) break;
    }
    #pragma unroll
    for (int i = 0; i < 8; i++) {
        int oc = oc0 + tr * 8 + i;
        float* dst; float bias = 0.f;
        if (oc < 64)        dst = g_q + ((size_t)b * DQ + oc) * Nn;
        else if (oc < 128)  dst = g_k + ((size_t)b * DQ + (oc - 64)) * Nn;
        else { dst = g_v + ((size_t)b * Cc + (oc - 128)) * Nn; bias = bv[oc - 128]; }
        #pragma unroll
        for (int j = 0; j < 8; j++) dst[n0 + tc * 8 + j] = acc[i][j] + bias;
    }
}

// ---------------------- qlt = q @ LT^T : [B,N,189] -----------------------------
__global__ __launch_bounds__(256) void qlt_kernel() {
    const int b = blockIdx.z, nt = blockIdx.y, rt = blockIdx.x;
    const int n0 = nt * 128, r0 = rt * 64;
    const int t = threadIdx.x, tr = t >> 4, tc = t & 15;
    __shared__ float Qs[64][128];
    __shared__ float Ls[64][64];
    const float* qb = g_q + (size_t)b * DQ * Nn + n0;
    #pragma unroll
    for (int u = 0; u < 8; u++) {
        int idx = (u * 256 + t) * 4;
        *(float4*)&Qs[idx >> 7][idx & 127] =
            *(const float4*)&qb[(size_t)(idx >> 7) * Nn + (idx & 127)];
    }
    #pragma unroll
    for (int u = 0; u < 4; u++) {
        int idx = (u * 256 + t) * 4;
        int rr = idx >> 6, kk = idx & 63;
        float4 w4 = make_float4(0.f, 0.f, 0.f, 0.f);
        if (r0 + rr < RR) w4 = *(const float4*)&g_LT[(r0 + rr) * DQ + kk];
        Ls[kk + 0][rr] = w4.x; Ls[kk + 1][rr] = w4.y;
        Ls[kk + 2][rr] = w4.z; Ls[kk + 3][rr] = w4.w;
    }
    __syncthreads();
    float acc[8][4] = {};
    #pragma unroll 8
    for (int kk = 0; kk < 64; kk++) {
        float4 a0 = *(float4*)&Qs[kk][tr * 8], a1 = *(float4*)&Qs[kk][tr * 8 + 4];
        float4 b0 = *(float4*)&Ls[kk][tc * 4];
        float a[8]  = {a0.x, a0.y, a0.z, a0.w, a1.x, a1.y, a1.z, a1.w};
        float bb[4] = {b0.x, b0.y, b0.z, b0.w};
        #pragma unroll
        for (int i = 0; i < 8; i++)
            #pragma unroll
            for (int j = 0; j < 4; j++)
                acc[i][j] += a[i] * bb[j];
    }
    #pragma unroll
    for (int i = 0; i < 8; i++) {
        int n = n0 + tr * 8 + i;
        float* dst = g_qlt + ((size_t)b * Nn + n) * RR;
        #pragma unroll
        for (int j = 0; j < 4; j++) {
            int rg = r0 + tc * 4 + j;
            if (rg < RR) dst[rg] = acc[i][j];
        }
    }
}

// ------------- gather per-row shifted bias tables T[b,n,ax*32+j] ---------------
__global__ void tgather_kernel() {
    int o = blockIdx.x * 256 + threadIdx.x;
    if (o >= Bz * Nn * 96) return;
    int ng = o / 96;
    int rem = o - ng * 96;
    int ax = rem >> 5, j = rem & 31;
    int dn = (g_dpack[ng] >> (5 * ax)) & 31;
    g_T[o] = g_qlt[(size_t)ng * RR + ax * 63 + j + 31 - dn];
}

// -------- pass A: E = exp(q.k + bias), row partial sums (deterministic) --------
// v2: Q/K staged in 2 chunks of 32 k-rows (smem 115KB -> 80.5KB => 2 CTAs/SM).
// Accumulation order (k ascending) identical to v1 => bit-exact output.
__global__ __launch_bounds__(256, 2) void energy_kernel() {
    extern __shared__ float sm[];
    float* Qs = sm;                 // [32][128]
    float* Ks = sm + 4096;          // [32][128]
    float* Ts = sm + 8192;          // [128][96]
    int*   Ds = (int*)(sm + 20480); // [128]
    const int b = blockIdx.z, nt = blockIdx.y, mt = blockIdx.x;
    const int n0 = nt * 128, m0 = mt * 128;
    const int t = threadIdx.x, tr = t >> 4, tc = t & 15;
    const float* qb = g_q + (size_t)b * DQ * Nn + n0;
    const float* kb = g_k + (size_t)b * DQ * Nn + m0;
    const float* tb = g_T + ((size_t)b * Nn + n0) * 96;
    #pragma unroll
    for (int u = 0; u < 12; u++) {
        int idx = (u * 256 + t) * 4;
        *(float4*)&Ts[idx] = *(const float4*)&tb[idx];
    }
    if (t < 128) Ds[t] = g_dpack[b * Nn + m0 + t];

    float acc[8][8] = {};
    #pragma unroll
    for (int ks0 = 0; ks0 < DQ; ks0 += 32) {
        __syncthreads();   // WAR: previous chunk's compute done before overwrite
        #pragma unroll
        for (int u = 0; u < 4; u++) {
            int idx = (u * 256 + t) * 4;
            int kk = idx >> 7, c = idx & 127;
            *(float4*)&Qs[idx] = *(const float4*)&qb[(size_t)(ks0 + kk) * Nn + c];
            *(float4*)&Ks[idx] = *(const float4*)&kb[(size_t)(ks0 + kk) * Nn + c];
        }
        __syncthreads();
        #pragma unroll 8
        for (int kk = 0; kk < 32; kk++) {
            float4 a0 = *(float4*)&Qs[kk * 128 + tr * 8];
            float4 a1 = *(float4*)&Qs[kk * 128 + tr * 8 + 4];
            float4 b0 = *(float4*)&Ks[kk * 128 + tc * 8];
            float4 b1 = *(float4*)&Ks[kk * 128 + tc * 8 + 4];
            float a[8]  = {a0.x, a0.y, a0.z, a0.w, a1.x, a1.y, a1.z, a1.w};
            float bb[8] = {b0.x, b0.y, b0.z, b0.w, b1.x, b1.y, b1.z, b1.w};
            #pragma unroll
            for (int i = 0; i < 8; i++)
                #pragma unroll
                for (int j = 0; j < 8; j++)
                    acc[i][j] += a[i] * bb[j];
        }
    }

    int dp[8];
    #pragma unroll
    for (int j = 0; j < 8; j++) dp[j] = Ds[tc * 8 + j];
    float* Eb = g_E + (size_t)b * NNsz;
    float rsum[8];
    #pragma unroll
    for (int i = 0; i < 8; i++) {
        const float* Tr = Ts + (tr * 8 + i) * 96;
        float o[8]; float rs = 0.f;
        #pragma unroll
        for (int j = 0; j < 8; j++) {
            int d = dp[j];
            float e = acc[i][j] + Tr[d & 31] + Tr[32 + ((d >> 5) & 31)]
                                + Tr[64 + ((d >> 10) & 31)];
            float v = __expf(e);   // |e| << 88: no max-subtraction needed
            o[j] = v; rs += v;
        }
        rsum[i] = rs;
        float* Er = Eb + (size_t)(n0 + tr * 8 + i) * Nn + m0 + tc * 8;
        *(float4*)&Er[0] = make_float4(o[0], o[1], o[2], o[3]);
        *(float4*)&Er[4] = make_float4(o[4], o[5], o[6], o[7]);
    }
    #pragma unroll
    for (int i = 0; i < 8; i++) {
        #pragma unroll
        for (int mk = 1; mk < 16; mk <<= 1)
            rsum[i] += __shfl_xor_sync(0xffffffffu, rsum[i], mk);
    }
    if (tc == 0) {
        float* rp = g_rowpart + mt * (Bz * Nn) + b * Nn + n0 + tr * 8;
        #pragma unroll
        for (int i = 0; i < 8; i++) rp[i] = rsum[i];
    }
}

__global__ void reduce_row_kernel() {
    int i = blockIdx.x * 256 + threadIdx.x;
    if (i >= Bz * Nn) return;
    float s = 0.f;
    #pragma unroll
    for (int p = 0; p < 16; p++) s += g_rowpart[p * (Bz * Nn) + i];
    g_rowinv[i] = 1.0f / s;
}

// ------ pass C (tf32 tensor cores): x_r = v @ (E*rowinv); xmr = x - x_r*colinv --
// CTA tile 128(d) x 128(m), K-chunk 32 over n. 8 warps as 2(d) x 4(m),
// warp tile 64x32 = 4x4 m16n8k8 tiles. Vs[d][36]: A-frag bank (4g+q)%32 distinct.
// Es[k][136]: B-frag bank (8q+g)%32 distinct.
// Column sums of attn are accumulated inline (each CTA sees all n for its m's):
// thread t owns fixed columns em=(4t)&127; rows 8u+w cover each n exactly once.
__global__ __launch_bounds__(256, 1) void xr_mma_kernel(const float* __restrict__ x) {
    const int b = blockIdx.z, dt = blockIdx.y, mt0 = blockIdx.x;
    const int d0 = dt * 128, m0 = mt0 * 128;
    const int t = threadIdx.x;
    const int w = t >> 5, l = t & 31;
    const int g = l >> 2, q = l & 3;
    const int wd = w >> 2, wm = w & 3;           // 2 x 4 warp grid
    __shared__ float Vs[128][36];
    __shared__ float Es[32][136];
    __shared__ float colacc[8][128];
    const float* vb = g_v + ((size_t)b * Cc + d0) * Nn;
    const float* Eb = g_E + (size_t)b * NNsz + m0;
    const float* ri = g_rowinv + b * Nn;

    float acc[16][4];
    #pragma unroll
    for (int i = 0; i < 16; i++)
        #pragma unroll
        for (int j = 0; j < 4; j++) acc[i][j] = 0.f;
    float cs[4] = {0.f, 0.f, 0.f, 0.f};          // colsum partials (fp32, pre-tf32)

    float4 vr[4], er[4];
    // prefetch chunk 0
    #pragma unroll
    for (int u = 0; u < 4; u++) {
        int e = (u * 256 + t) * 4;
        vr[u] = *(const float4*)&vb[(size_t)(e >> 5) * Nn + (e & 31)];
        int ek = e >> 7, em = e & 127;
        float s = ri[ek];
        float4 e4 = *(const float4*)&Eb[(size_t)ek * Nn + em];
        er[u] = make_float4(e4.x * s, e4.y * s, e4.z * s, e4.w * s);
    }

    int k0 = 0;
    while (true) {
        #pragma unroll
        for (int u = 0; u < 4; u++) {
            int e = (u * 256 + t) * 4;
            int vd = e >> 5, vk = e & 31;
            Vs[vd][vk + 0] = cvt_tf32(vr[u].x);
            Vs[vd][vk + 1] = cvt_tf32(vr[u].y);
            Vs[vd][vk + 2] = cvt_tf32(vr[u].z);
            Vs[vd][vk + 3] = cvt_tf32(vr[u].w);
            cs[0] += er[u].x; cs[1] += er[u].y;   // exact attn colsum partials
            cs[2] += er[u].z; cs[3] += er[u].w;
            int ek = e >> 7, em = e & 127;
            float4 c4 = make_float4(cvt_tf32(er[u].x), cvt_tf32(er[u].y),
                                    cvt_tf32(er[u].z), cvt_tf32(er[u].w));
            *(float4*)&Es[ek][em] = c4;
        }
        __syncthreads();
        k0 += 32;
        bool more = (k0 < Nn);
        if (more) {
            #pragma unroll
            for (int u = 0; u < 4; u++) {
                int e = (u * 256 + t) * 4;
                vr[u] = *(const float4*)&vb[(size_t)(e >> 5) * Nn + k0 + (e & 31)];
                int ek = e >> 7, em = e & 127;
                float s = ri[k0 + ek];
                float4 e4 = *(const float4*)&Eb[(size_t)(k0 + ek) * Nn + em];
                er[u] = make_float4(e4.x * s, e4.y * s, e4.z * s, e4.w * s);
            }
        }
        #pragma unroll
        for (int ks = 0; ks < 4; ks++) {
            const int kb = ks * 8;
            unsigned A[4][4], Bf[4][2];
            #pragma unroll
            for (int mt = 0; mt < 4; mt++) {
                int row = wd * 64 + mt * 16 + g;
                A[mt][0] = __float_as_uint(Vs[row][kb + q]);
                A[mt][1] = __float_as_uint(Vs[row + 8][kb + q]);
                A[mt][2] = __float_as_uint(Vs[row][kb + q + 4]);
                A[mt][3] = __float_as_uint(Vs[row + 8][kb + q + 4]);
            }
            #pragma unroll
            for (int nt = 0; nt < 4; nt++) {
                int col = wm * 32 + nt * 8 + g;
                Bf[nt][0] = __float_as_uint(Es[kb + q][col]);
                Bf[nt][1] = __float_as_uint(Es[kb + q + 4][col]);
            }
            #pragma unroll
            for (int mt = 0; mt < 4; mt++)
                #pragma unroll
                for (int nt = 0; nt < 4; nt++)
                    mma_tf32(acc[mt * 4 + nt], A[mt], Bf[nt]);
        }
        __syncthreads();
        if (!more) break;
    }

    // publish colsum partials: thread t owns columns em..em+3, slice = warp id
    {
        int em = (4 * t) & 127;
        *(float4*)&colacc[w][em] = *(float4*)cs;
    }
    __syncthreads();

    // epilogue: xmr = x - x_r * colinv   (colinv from 8-slice deterministic sum)
    #pragma unroll
    for (int nt = 0; nt < 4; nt++) {
        int cl = wm * 32 + nt * 8 + q * 2;       // local column in [0,128)
        float s0 = 0.f, s1 = 0.f;
        #pragma unroll
        for (int ws = 0; ws < 8; ws++) {
            s0 += colacc[ws][cl];
            s1 += colacc[ws][cl + 1];
        }
        float ci0 = 1.0f / (1e-9f + s0);
        float ci1 = 1.0f / (1e-9f + s1);
        int mloc = m0 + cl;
        #pragma unroll
        for (int mt = 0; mt < 4; mt++) {
            int d1 = d0 + wd * 64 + mt * 16 + g;
            const float* c = acc[mt * 4 + nt];
            {
                const float* xp = x + ((size_t)b * Cc + d1) * Nn + mloc;
                float* op = g_xmr + ((size_t)b * Cc + d1) * Nn + mloc;
                float2 o = make_float2(xp[0] - c[0] * ci0, xp[1] - c[1] * ci1);
                *(float2*)op = o;
            }
            {
                const float* xp = x + ((size_t)b * Cc + d1 + 8) * Nn + mloc;
                float* op = g_xmr + ((size_t)b * Cc + d1 + 8) * Nn + mloc;
                float2 o = make_float2(xp[0] - c[2] * ci0, xp[1] - c[3] * ci1);
                *(float2*)op = o;
            }
        }
    }
}

// ------- pass D: out = x + relu(BN(Wt @ xmr + bt)) ------------------------------
__global__ __launch_bounds__(256, 2) void trans_kernel(
    const float* __restrict__ x, const float* __restrict__ Wt,
    const float* __restrict__ bt, const float* __restrict__ gamma,
    const float* __restrict__ beta, const float* __restrict__ rmean,
    const float* __restrict__ rvar, float* __restrict__ out) {
    const int b = blockIdx.z, ot = blockIdx.y, mt = blockIdx.x;
    const int o0 = ot * 128, m0 = mt * 128;
    const int t = threadIdx.x, tr = t >> 4, tc = t & 15;
    __shared__ float Ws[32][132];
    __shared__ float Xs[32][132];
    const float* xb = g_xmr + (size_t)b * Cc * Nn + m0;
    float acc[8][8] = {};
    float4 wr[4], xr4[4];
    #pragma unroll
    for (int u = 0; u < 4; u++) {
        int idx = (u * 256 + t) * 4;
        wr[u]  = *(const float4*)&Wt[(o0 + (idx >> 5)) * Cc + (idx & 31)];
        xr4[u] = *(const float4*)&xb[(size_t)(idx >> 7) * Nn + (idx & 127)];
    }
    int k0 = 0;
    while (true) {
        #pragma unroll
        for (int u = 0; u < 4; u++) {
            int idx = (u * 256 + t) * 4;
            int oc = idx >> 5, kk = idx & 31;
            Ws[kk + 0][oc] = wr[u].x; Ws[kk + 1][oc] = wr[u].y;
            Ws[kk + 2][oc] = wr[u].z; Ws[kk + 3][oc] = wr[u].w;
            *(float4*)&Xs[idx >> 7][idx & 127] = xr4[u];
        }
        __syncthreads();
        k0 += 32;
        bool more = (k0 < Cc);
        if (more) {
            #pragma unroll
            for (int u = 0; u < 4; u++) {
                int idx = (u * 256 + t) * 4;
                wr[u]  = *(const float4*)&Wt[(o0 + (idx >> 5)) * Cc + k0 + (idx & 31)];
                xr4[u] = *(const float4*)&xb[(size_t)(k0 + (idx >> 7)) * Nn + (idx & 127)];
            }
        }
        #pragma unroll 8
        for (int kk = 0; kk < 32; kk++) {
            float4 a0 = *(float4*)&Ws[kk][tr * 8], a1 = *(float4*)&Ws[kk][tr * 8 + 4];
            float4 b0 = *(float4*)&Xs[kk][tc * 8], b1 = *(float4*)&Xs[kk][tc * 8 + 4];
            float a[8]  = {a0.x, a0.y, a0.z, a0.w, a1.x, a1.y, a1.z, a1.w};
            float bb[8] = {b0.x, b0.y, b0.z, b0.w, b1.x, b1.y, b1.z, b1.w};
            #pragma unroll
            for (int i = 0; i < 8; i++)
                #pragma unroll
                for (int j = 0; j < 8; j++)
                    acc[i][j] += a[i] * bb[j];
        }
        __syncthreads();
        if (!more) break;
    }
    #pragma unroll
    for (int i = 0; i < 8; i++) {
        int oc = o0 + tr * 8 + i;
        float inv = gamma[oc] * rsqrtf(rvar[oc] + 1e-5f);
        float mb  = bt[oc] - rmean[oc];
        float be  = beta[oc];
        const float* xrow = x + ((size_t)b * Cc + oc) * Nn + m0 + tc * 8;
        float* orow = out + ((size_t)b * Cc + oc) * Nn + m0 + tc * 8;
        #pragma unroll
        for (int j = 0; j < 8; j++) {
            float y = (acc[i][j] + mb) * inv + be;
            orow[j] = xrow[j] + fmaxf(y, 0.f);
        }
    }
}

// ------------------------------- launch ----------------------------------------
extern "C" void kernel_launch(void* const* d_in, const int* in_sizes, int n_in,
                              void* d_out, int out_size) {
    const float* x        = (const float*)d_in[0];
    const int*   discrete = (const int*)  d_in[1];
    // d_in[2] = xyz (unused by the reference math)
    const float* Wq    = (const float*)d_in[3];
    const float* Wk    = (const float*)d_in[4];
    const float* Wv    = (const float*)d_in[5];
    const float* bv    = (const float*)d_in[6];
    const float* x_lt  = (const float*)d_in[7];
    const float* y_lt  = (const float*)d_in[8];
    const float* z_lt  = (const float*)d_in[9];
    const float* Wt    = (const float*)d_in[10];
    const float* bt    = (const float*)d_in[11];
    const float* gamma = (const float*)d_in[12];
    const float* beta  = (const float*)d_in[13];
    const float* rmean = (const float*)d_in[14];
    const float* rvar  = (const float*)d_in[15];
    float* out = (float*)d_out;

    static const size_t kEnergySmem = 20480 * sizeof(float) + 128 * sizeof(int);
    cudaFuncSetAttribute(energy_kernel,
                         cudaFuncAttributeMaxDynamicSharedMemorySize,
                         (int)kEnergySmem);

    prep_kernel<<<(384 * Cc + 255) / 256, 256>>>(Wq, Wk, Wv, x_lt, y_lt, z_lt, discrete);

    dim3 g1(Nn / 128, 3, Bz);
    qkv_kernel<<<g1, 256>>>(x, bv);

    dim3 g2(3, Nn / 128, Bz);
    qlt_kernel<<<g2, 256>>>();

    tgather_kernel<<<(Bz * Nn * 96 + 255) / 256, 256>>>();

    dim3 g3(Nn / 128, Nn / 128, Bz);
    energy_kernel<<<g3, 256, kEnergySmem>>>();

    reduce_row_kernel<<<(Bz * Nn + 255) / 256, 256>>>();

    dim3 g5(Nn / 128, Cc / 128, Bz);
    xr_mma_kernel<<<g5, 256>>>(x);

    dim3 g6(Nn / 128, Cc / 128, Bz);
    trans_kernel<<<g6, 256>>>(x, Wt, bt, gamma, beta, rmean, rvar, out);
}